// round 2
// baseline (speedup 1.0000x reference)
#include <cuda_runtime.h>

#define FULLMASK 0xffffffffu

namespace {
constexpr int BB = 256;
constexpr int TT = 2048;
constexpr int DD = 64;
constexpr int LBAND = 2;
constexpr int DB = 32;
constexpr int GG = 96;
constexpr int PADW = 36;    // padded row stride (floats) -> conflict-free LDS.128
constexpr int TPAD = TT + 32;  // dt rows padded so the 32-wide prefetch never reads OOB
}

// Scratch (module-static device globals; no runtime allocation)
__device__ float g_pdt[LBAND][BB][TPAD];
__device__ int   g_nv[LBAND][BB];
__device__ float g_c0[LBAND][BB][GG];
__device__ float g_c1[LBAND][BB][GG];

// ---------------------------------------------------------------------------
// Kernel 1: stable compaction of valid dtime values per (band,row) + counts
// ---------------------------------------------------------------------------
__global__ void compact_kernel(const int* __restrict__ band_ids,
                               const float* __restrict__ dtime) {
    int warp = threadIdx.x >> 5;
    int lane = threadIdx.x & 31;
    int b = blockIdx.x * (blockDim.x >> 5) + warp;
    if (b >= BB) return;
    int cnt0 = 0, cnt1 = 0;
    for (int base = 0; base < TT; base += 32) {
        int t = base + lane;
        int id = band_ids[b * TT + t];
        float dt = dtime[b * TT + t];
        unsigned m0 = __ballot_sync(FULLMASK, id == 0);
        unsigned lt = (1u << lane) - 1u;
        if (id == 0) {
            g_pdt[0][b][cnt0 + __popc(m0 & lt)] = dt;
        } else {
            g_pdt[1][b][cnt1 + __popc((~m0) & lt)] = dt;
        }
        int p0 = __popc(m0);
        cnt0 += p0;
        cnt1 += 32 - p0;
    }
    if (lane == 0) { g_nv[0][b] = cnt0; g_nv[1][b] = cnt1; }
}

// ---------------------------------------------------------------------------
// Kernel 2: per-(band,row) affine layer-1 gate constants:
//   gx1_t = c0 + dt_t * c1,  c0 = Wih1@(z@projW + pb) + bih1, c1 = Wih1@projW[D]
// ---------------------------------------------------------------------------
__global__ void rowconst_kernel(const float* __restrict__ z_last,
                                const float* __restrict__ proj_W,
                                const float* __restrict__ proj_b,
                                const float* __restrict__ Wih,
                                const float* __restrict__ bih) {
    int warp = threadIdx.x >> 5;
    int lane = threadIdx.x & 31;
    int wg = blockIdx.x * (blockDim.x >> 5) + warp;
    if (wg >= LBAND * BB) return;
    int kb = wg >> 8;    // / 256
    int b  = wg & 255;

    float base = proj_b[kb * DB + lane];
#pragma unroll 8
    for (int i = 0; i < DD; i++) {
        base = fmaf(z_last[b * DD + i],
                    proj_W[(kb * (DD + 1) + i) * DB + lane], base);
    }
    float w65 = proj_W[(kb * (DD + 1) + DD) * DB + lane];

    for (int gi = 0; gi < 3; gi++) {
        int g = lane + 32 * gi;
        float c0a = bih[(kb * 2 + 0) * GG + g];
        float c1a = 0.f;
        for (int j = 0; j < DB; j++) {
            float bj = __shfl_sync(FULLMASK, base, j);
            float wj = __shfl_sync(FULLMASK, w65, j);
            float w  = Wih[((kb * 2 + 0) * GG + g) * DB + j];
            c0a = fmaf(w, bj, c0a);
            c1a = fmaf(w, wj, c1a);
        }
        g_c0[kb][b][g] = c0a;
        g_c1[kb][b][g] = c1a;
    }
}

// ---------------------------------------------------------------------------
// Main GRU kernel: 1 warp per (band,row) sequence; 4 warps/block share weights
// ---------------------------------------------------------------------------
__device__ __forceinline__ float fast_sigmoid(float x) {
    return __fdividef(1.0f, 1.0f + __expf(-x));
}
__device__ __forceinline__ float fast_tanh(float x) {
    return __fdividef(2.0f, 1.0f + __expf(-2.0f * x)) - 1.0f;
}

// 96x32 matvec over warp-distributed h (lane owns rows lane, lane+32, lane+64)
#define MATVEC(SW, hv, aR, aZ, aN) do {                                        \
    const float4* r0p = reinterpret_cast<const float4*>(&SW[lane][0]);         \
    const float4* r1p = reinterpret_cast<const float4*>(&SW[lane + 32][0]);    \
    const float4* r2p = reinterpret_cast<const float4*>(&SW[lane + 64][0]);    \
    _Pragma("unroll")                                                          \
    for (int d4 = 0; d4 < 8; d4++) {                                           \
        float4 w0 = r0p[d4]; float4 w1 = r1p[d4]; float4 w2 = r2p[d4];         \
        float ha = __shfl_sync(FULLMASK, hv, 4 * d4 + 0);                      \
        float hb = __shfl_sync(FULLMASK, hv, 4 * d4 + 1);                      \
        float hc = __shfl_sync(FULLMASK, hv, 4 * d4 + 2);                      \
        float hd = __shfl_sync(FULLMASK, hv, 4 * d4 + 3);                      \
        aR = fmaf(w0.x, ha, aR); aZ = fmaf(w1.x, ha, aZ); aN = fmaf(w2.x, ha, aN); \
        aR = fmaf(w0.y, hb, aR); aZ = fmaf(w1.y, hb, aZ); aN = fmaf(w2.y, hb, aN); \
        aR = fmaf(w0.z, hc, aR); aZ = fmaf(w1.z, hc, aZ); aN = fmaf(w2.z, hc, aN); \
        aR = fmaf(w0.w, hd, aR); aZ = fmaf(w1.w, hd, aZ); aN = fmaf(w2.w, hd, aN); \
    }                                                                          \
} while (0)

__global__ __launch_bounds__(128, 1)
void gru_main_kernel(const float* __restrict__ Wih,
                     const float* __restrict__ Whh,
                     const float* __restrict__ bih,
                     const float* __restrict__ bhh,
                     const float* __restrict__ mW1,
                     const float* __restrict__ mb1,
                     const float* __restrict__ mW2,
                     const float* __restrict__ mb2,
                     float* __restrict__ out) {
    __shared__ __align__(16) float sWhh1[GG][PADW];
    __shared__ __align__(16) float sWih2[GG][PADW];
    __shared__ __align__(16) float sWhh2[GG][PADW];
    __shared__ __align__(16) float sM1[DB][DB];   // mW1[d][j], bank-conflict-free

    const int kb   = blockIdx.x >> 6;
    const int bgrp = blockIdx.x & 63;
    const int wid  = threadIdx.x >> 5;
    const int lane = threadIdx.x & 31;
    const int b    = bgrp * 4 + wid;

    // Cooperative weight staging (band kb)
    for (int idx = threadIdx.x; idx < GG * DB; idx += blockDim.x) {
        int g = idx >> 5, d = idx & 31;
        sWhh1[g][d] = Whh[(kb * 2 + 0) * GG * DB + idx];
        sWih2[g][d] = Wih[(kb * 2 + 1) * GG * DB + idx];
        sWhh2[g][d] = Whh[(kb * 2 + 1) * GG * DB + idx];
    }
    for (int idx = threadIdx.x; idx < DB * DB; idx += blockDim.x) {
        sM1[idx >> 5][idx & 31] = mW1[kb * DB * DB + idx];
    }
    __syncthreads();

    // Per-lane constants (lane owns gate rows lane/+32/+64)
    const float c0r = g_c0[kb][b][lane];
    const float c0z = g_c0[kb][b][lane + 32];
    const float c0n = g_c0[kb][b][lane + 64];
    const float c1r = g_c1[kb][b][lane];
    const float c1z = g_c1[kb][b][lane + 32];
    const float c1n = g_c1[kb][b][lane + 64];
    const float bh1r = bhh[(kb * 2 + 0) * GG + lane];
    const float bh1z = bhh[(kb * 2 + 0) * GG + lane + 32];
    const float bh1n = bhh[(kb * 2 + 0) * GG + lane + 64];
    const float bi2r = bih[(kb * 2 + 1) * GG + lane];
    const float bi2z = bih[(kb * 2 + 1) * GG + lane + 32];
    const float bi2n = bih[(kb * 2 + 1) * GG + lane + 64];
    const float bh2r = bhh[(kb * 2 + 1) * GG + lane];
    const float bh2z = bhh[(kb * 2 + 1) * GG + lane + 32];
    const float bh2n = bhh[(kb * 2 + 1) * GG + lane + 64];
    const float mb1l = mb1[kb * DB + lane];
    const float mw2l = mW2[kb * DB + lane];
    const float mb2s = mb2[kb];

    const int nv = g_nv[kb][b];
    float* __restrict__ orow = out + ((size_t)kb * BB + b) * TT;

    float h1 = 0.f, h2 = 0.f;
    float dtv = 0.f;

    for (int i = 0; i < nv; i++) {
        if ((i & 31) == 0) dtv = g_pdt[kb][b][i + lane];  // TPAD padding: never OOB
        float dt = __shfl_sync(FULLMASK, dtv, i & 31);

        // Independent recurrent matvecs first (6 FMA chains of ILP)
        float a1r = bh1r, a1z = bh1z, a1n = bh1n;
        float a2r = bh2r, a2z = bh2z, a2n = bh2n;
        MATVEC(sWhh1, h1, a1r, a1z, a1n);
        MATVEC(sWhh2, h2, a2r, a2z, a2n);

        // Layer-1 gates (gx1 is affine in dt)
        float r1 = fast_sigmoid(fmaf(dt, c1r, c0r) + a1r);
        float z1 = fast_sigmoid(fmaf(dt, c1z, c0z) + a1z);
        float n1 = fast_tanh(fmaf(dt, c1n, c0n) + r1 * a1n);
        h1 = fmaf(z1, h1 - n1, n1);            // (1-z)*n + z*h

        // Layer-2 input gates from new h1
        float g2r = bi2r, g2z = bi2z, g2n = bi2n;
        MATVEC(sWih2, h1, g2r, g2z, g2n);

        float r2 = fast_sigmoid(g2r + a2r);
        float z2 = fast_sigmoid(g2z + a2z);
        float n2 = fast_tanh(g2n + r2 * a2n);
        h2 = fmaf(z2, h2 - n2, n2);

        // Output MLP: y = relu(h2@mW1 + mb1)@mW2 + mb2
        float hidA = mb1l, hidB = 0.f;
#pragma unroll
        for (int d = 0; d < DB; d += 2) {
            float hd0 = __shfl_sync(FULLMASK, h2, d);
            float hd1 = __shfl_sync(FULLMASK, h2, d + 1);
            hidA = fmaf(hd0, sM1[d][lane], hidA);
            hidB = fmaf(hd1, sM1[d + 1][lane], hidB);
        }
        float hid = fmaxf(hidA + hidB, 0.f);
        float p = hid * mw2l;
#pragma unroll
        for (int off = 16; off > 0; off >>= 1)
            p += __shfl_xor_sync(FULLMASK, p, off);
        if (lane == 0) orow[i] = p + mb2s;
    }

    // Tail fill: masked steps hold h, so y is constant for i >= nv
    {
        float hidA = mb1l, hidB = 0.f;
#pragma unroll
        for (int d = 0; d < DB; d += 2) {
            float hd0 = __shfl_sync(FULLMASK, h2, d);
            float hd1 = __shfl_sync(FULLMASK, h2, d + 1);
            hidA = fmaf(hd0, sM1[d][lane], hidA);
            hidB = fmaf(hd1, sM1[d + 1][lane], hidB);
        }
        float hid = fmaxf(hidA + hidB, 0.f);
        float p = hid * mw2l;
#pragma unroll
        for (int off = 16; off > 0; off >>= 1)
            p += __shfl_xor_sync(FULLMASK, p, off);
        float y = p + mb2s;                    // butterfly leaves sum in all lanes
        for (int idx = nv + lane; idx < TT; idx += 32) orow[idx] = y;
    }
}

// ---------------------------------------------------------------------------
extern "C" void kernel_launch(void* const* d_in, const int* in_sizes, int n_in,
                              void* d_out, int out_size) {
    const int*   band_ids = (const int*)  d_in[0];
    const float* dtime    = (const float*)d_in[1];
    const float* z_last   = (const float*)d_in[2];
    const float* proj_W   = (const float*)d_in[3];
    const float* proj_b   = (const float*)d_in[4];
    const float* Wih      = (const float*)d_in[5];
    const float* Whh      = (const float*)d_in[6];
    const float* bih      = (const float*)d_in[7];
    const float* bhh      = (const float*)d_in[8];
    const float* mW1      = (const float*)d_in[9];
    const float* mb1      = (const float*)d_in[10];
    const float* mW2      = (const float*)d_in[11];
    const float* mb2      = (const float*)d_in[12];
    float* out = (float*)d_out;

    compact_kernel<<<BB / 8, 256>>>(band_ids, dtime);
    rowconst_kernel<<<(LBAND * BB) / 4, 128>>>(z_last, proj_W, proj_b, Wih, bih);
    gru_main_kernel<<<128, 128>>>(Wih, Whh, bih, bhh, mW1, mb1, mW2, mb2, out);
}